// round 14
// baseline (speedup 1.0000x reference)
#include <cuda_runtime.h>
#include <cuda_bf16.h>
#include <math.h>

#define BB 8
#define TT 2048
#define DD 512
#define KQ 32
#define NROWS (BB*TT)          // 16384
#define NCTA2 64               // persistent system2 CTAs

// ---------------- device scratch (__device__ globals: allocation-free rule) ----------------
__device__ float g_q[NROWS*KQ];
__device__ float g_k[NROWS*KQ];
__device__ float g_gathered[NROWS*DD];        // 32MB
__device__ float g_h1[NROWS*2*DD];            // 64MB
__device__ float g_y[NROWS*DD];               // 32MB
__device__ float g_ytp[TT*BB*2*DD];           // 64MB, timestep-major [t][b][1024], includes bt1
__device__ float g_hstep[BB*2*DD];            // per-step hidden after gelu [b][1024]
__device__ float g_mem[BB*DD];                // current memory [b][512]
__device__ unsigned g_arrive;                 // barrier ticket counter
__device__ volatile unsigned g_gen;           // barrier generation

__device__ __forceinline__ float gelu_f(float x) {
    return 0.5f * x * (1.0f + erff(x * 0.70710678118654752f));
}

// ---------------- K1: q/k projections ----------------
__global__ void qk_kernel(const float* __restrict__ x,
                          const float* __restrict__ Wq, const float* __restrict__ bq,
                          const float* __restrict__ Wk, const float* __restrict__ bk) {
    int r = blockIdx.x;              // 0..16383
    __shared__ float xs[DD];
    int tid = threadIdx.x;           // 128
    ((float4*)xs)[tid] = ((const float4*)(x + (size_t)r*DD))[tid];
    __syncthreads();
    int o = tid >> 1;                // 0..63 ; 0..31 -> q cols, 32..63 -> k cols
    int half = tid & 1;
    int j = o & 31;
    const float* W = (o < 32) ? Wq : Wk;
    float s = 0.f;
    #pragma unroll 8
    for (int d = half; d < DD; d += 2) s = fmaf(xs[d], W[d*KQ + j], s);
    s += __shfl_down_sync(0xffffffffu, s, 1);
    if (half == 0) {
        float bias = (o < 32) ? bq[j] : bk[j];
        float* out = (o < 32) ? g_q : g_k;
        out[(size_t)r*KQ + j] = s + bias;
    }
}

// ---------------- K2: per-row top-4 + gather-mean ----------------
__global__ void topk_gather(const float* __restrict__ x) {
    int b = blockIdx.y;
    int t0 = blockIdx.x * 128;
    int tid = threadIdx.x;           // 128; each owns one t-row
    __shared__ float sk[128*KQ];
    __shared__ int sidx[128][4];

    float4 q4[8];
    const float4* qr = (const float4*)(g_q + ((size_t)b*TT + t0 + tid)*KQ);
    #pragma unroll
    for (int i = 0; i < 8; i++) q4[i] = qr[i];

    float v0=-3.4e38f, v1=-3.4e38f, v2=-3.4e38f, v3=-3.4e38f;
    int i0=0, i1=0, i2=0, i3=0;

    for (int s0 = 0; s0 < TT; s0 += 128) {
        __syncthreads();
        const float4* kr = (const float4*)(g_k + ((size_t)b*TT + s0)*KQ);
        #pragma unroll
        for (int i = 0; i < 8; i++) ((float4*)sk)[tid + i*128] = kr[tid + i*128];
        __syncthreads();
        for (int ss = 0; ss < 128; ss++) {
            const float4* kk = (const float4*)(sk + ss*KQ);
            float sim = 0.f;
            #pragma unroll
            for (int i = 0; i < 8; i++) {
                float4 kv = kk[i];
                sim += q4[i].x*kv.x + q4[i].y*kv.y + q4[i].z*kv.z + q4[i].w*kv.w;
            }
            int s = s0 + ss;
            if (sim > v3) {                      // strict > : earlier index wins ties (jax top_k)
                if (sim > v1) {
                    if (sim > v0) { v3=v2;i3=i2; v2=v1;i2=i1; v1=v0;i1=i0; v0=sim;i0=s; }
                    else          { v3=v2;i3=i2; v2=v1;i2=i1; v1=sim;i1=s; }
                } else {
                    if (sim > v2) { v3=v2;i3=i2; v2=sim;i2=s; }
                    else          { v3=sim;i3=s; }
                }
            }
        }
    }
    sidx[tid][0]=i0; sidx[tid][1]=i1; sidx[tid][2]=i2; sidx[tid][3]=i3;
    __syncthreads();

    int d = tid * 4;  // cooperative gather-mean: 128 threads x 4 dims per row
    for (int tt = 0; tt < 128; tt++) {
        int j0 = sidx[tt][0], j1 = sidx[tt][1], j2 = sidx[tt][2], j3 = sidx[tt][3];
        float4 a = *(const float4*)(x + ((size_t)b*TT + j0)*DD + d);
        float4 c = *(const float4*)(x + ((size_t)b*TT + j1)*DD + d);
        float4 e = *(const float4*)(x + ((size_t)b*TT + j2)*DD + d);
        float4 f = *(const float4*)(x + ((size_t)b*TT + j3)*DD + d);
        float4 o;
        o.x = 0.25f*(a.x + c.x + e.x + f.x);
        o.y = 0.25f*(a.y + c.y + e.y + f.y);
        o.z = 0.25f*(a.z + c.z + e.z + f.z);
        o.w = 0.25f*(a.w + c.w + e.w + f.w);
        *(float4*)(g_gathered + ((size_t)b*TT + t0 + tt)*DD + d) = o;
    }
}

// ---------------- 128x128x8 fp32 SGEMM, 256 threads, 8x8 micro-tile ----------------
// MODE 0: C = gelu(A@B + bias)
// MODE 1: C = A@B + bias + res
// MODE 2: C[t*8192 + b*1024 + c] = A@B + bias   (scatter to timestep-major)
template<int MODE>
__global__ void __launch_bounds__(256) sgemm_k(
    const float* __restrict__ A, const float* __restrict__ B,
    float* __restrict__ C, const float* __restrict__ bias,
    const float* __restrict__ res, int M, int N, int K, int ldb)
{
    __shared__ float As[8][128];
    __shared__ float Bs[8][128];
    const int tid = threadIdx.x;
    const int tx = tid & 15, ty = tid >> 4;
    const int row0 = blockIdx.y * 128, col0 = blockIdx.x * 128;
    const int arow = tid >> 1, acol = (tid & 1) << 2;
    const int brow = tid >> 5, bcol = (tid & 31) << 2;
    const float* Ap = A + (size_t)(row0 + arow) * K + acol;
    const float* Bp = B + (size_t)brow * ldb + col0 + bcol;
    float acc[8][8];
    #pragma unroll
    for (int i = 0; i < 8; i++)
        #pragma unroll
        for (int j = 0; j < 8; j++) acc[i][j] = 0.f;

    for (int k0 = 0; k0 < K; k0 += 8) {
        float4 av = *(const float4*)Ap; Ap += 8;
        float4 bv = *(const float4*)Bp; Bp += (size_t)8 * ldb;
        As[acol+0][arow] = av.x; As[acol+1][arow] = av.y;
        As[acol+2][arow] = av.z; As[acol+3][arow] = av.w;
        *(float4*)&Bs[brow][bcol] = bv;
        __syncthreads();
        #pragma unroll
        for (int kk = 0; kk < 8; kk++) {
            float a[8], bb2[8];
            *(float4*)&a[0]   = *(const float4*)&As[kk][ty*4];
            *(float4*)&a[4]   = *(const float4*)&As[kk][64 + ty*4];
            *(float4*)&bb2[0] = *(const float4*)&Bs[kk][tx*4];
            *(float4*)&bb2[4] = *(const float4*)&Bs[kk][64 + tx*4];
            #pragma unroll
            for (int i = 0; i < 8; i++)
                #pragma unroll
                for (int j = 0; j < 8; j++)
                    acc[i][j] = fmaf(a[i], bb2[j], acc[i][j]);
        }
        __syncthreads();
    }

    #pragma unroll
    for (int ih = 0; ih < 2; ih++)
    #pragma unroll
    for (int ii = 0; ii < 4; ii++) {
        int r = row0 + ih*64 + ty*4 + ii;
        #pragma unroll
        for (int jh = 0; jh < 2; jh++) {
            int c = col0 + jh*64 + tx*4;
            float4 v;
            v.x = acc[ih*4+ii][jh*4+0] + bias[c+0];
            v.y = acc[ih*4+ii][jh*4+1] + bias[c+1];
            v.z = acc[ih*4+ii][jh*4+2] + bias[c+2];
            v.w = acc[ih*4+ii][jh*4+3] + bias[c+3];
            if (MODE == 0) {
                v.x = gelu_f(v.x); v.y = gelu_f(v.y); v.z = gelu_f(v.z); v.w = gelu_f(v.w);
                *(float4*)(C + (size_t)r*N + c) = v;
            } else if (MODE == 1) {
                float4 rv = *(const float4*)(res + (size_t)r*N + c);
                v.x += rv.x; v.y += rv.y; v.z += rv.z; v.w += rv.w;
                *(float4*)(C + (size_t)r*N + c) = v;
            } else {
                int t = r & (TT-1), b = r >> 11;
                *(float4*)(C + (size_t)t*(BB*2*DD) + (size_t)b*(2*DD) + c) = v;
            }
        }
    }
}

// ---------------- LayerNorm over last dim (512), in place ----------------
__global__ void ln_kernel(float* __restrict__ y,
                          const float* __restrict__ g, const float* __restrict__ bta) {
    int r = blockIdx.x, tid = threadIdx.x;   // 256 threads
    float2 v = ((const float2*)(y + (size_t)r*DD))[tid];
    float s = v.x + v.y;
    float ss = v.x*v.x + v.y*v.y;
    #pragma unroll
    for (int o = 16; o; o >>= 1) {
        s  += __shfl_down_sync(0xffffffffu, s, o);
        ss += __shfl_down_sync(0xffffffffu, ss, o);
    }
    __shared__ float as_[8], bs_[8];
    int w = tid >> 5, l = tid & 31;
    if (l == 0) { as_[w] = s; bs_[w] = ss; }
    __syncthreads();
    if (tid == 0) {
        float S = 0.f, SS = 0.f;
        #pragma unroll
        for (int i = 0; i < 8; i++) { S += as_[i]; SS += bs_[i]; }
        as_[0] = S; bs_[0] = SS;
    }
    __syncthreads();
    float mu  = as_[0] * (1.0f/512.0f);
    float var = bs_[0] * (1.0f/512.0f) - mu*mu;
    float inv = rsqrtf(var + 1e-5f);
    float2 o;
    o.x = (v.x - mu)*inv*g[2*tid]   + bta[2*tid];
    o.y = (v.y - mu)*inv*g[2*tid+1] + bta[2*tid+1];
    ((float2*)(y + (size_t)r*DD))[tid] = o;
}

// ---------------- grid barrier (monotonic ticket, tight poll) ----------------
__device__ __forceinline__ void grid_barrier(unsigned target) {
    __threadfence();               // release my prior global writes
    __syncthreads();
    if (threadIdx.x == 0) {
        unsigned ticket = atomicAdd(&g_arrive, 1u);
        if (ticket == target * NCTA2 - 1u) {
            g_gen = target;        // release store after strong atomic
        } else {
            while (g_gen < target) { }   // tight poll: detection ~1 L2 round trip
        }
        __threadfence();           // acquire
    }
    __syncthreads();
}

__global__ void s2_reset() { g_arrive = 0u; g_gen = 0u; }

// ---------------- System2: persistent cooperative recurrence (64 CTAs) ----------------
// CTA ci owns h-cols [16ci,16ci+16) and prop/mem-cols [8ci,8ci+8); weights stationary in SMEM.
__global__ void __launch_bounds__(512, 1) s2_kernel(
    const float* __restrict__ Wt1, const float* __restrict__ Wt2,
    const float* __restrict__ bt2)
{
    extern __shared__ float sm[];
    float* sW1    = sm;                 // 16 x 516   (W1t[c][k], k=0..511)
    float* sW2    = sW1 + 16*516;       // 8 x 1028   (W2t[c][k], k=0..1023)
    float* sStage = sW2 + 8*1028;       // 8 x 1028   (mem rows use 516-float stride view)
    float* sRed   = sStage + 8*1028;    // 512
    float* sMemL  = sRed + 512;         // 64 : this CTA's mem slice [b][cb]
    float* sb2    = sMemL + 64;         // 8

    const int tid = threadIdx.x;
    const int ci = blockIdx.x;
    const int col0 = ci * 16;
    const int ocol0 = ci * 8;

    #pragma unroll
    for (int rep = 0; rep < 16; rep++) {            // 16 cols x 512 k
        int i = tid + rep*512;
        int c = i >> 9, k = i & 511;
        sW1[c*516 + k] = Wt1[(size_t)(512 + k)*1024 + col0 + c];
    }
    #pragma unroll
    for (int rep = 0; rep < 16; rep++) {            // 8 cols x 1024 k
        int i = tid + rep*512;
        int c = i >> 10, k = i & 1023;
        sW2[c*1028 + k] = Wt2[(size_t)k*512 + ocol0 + c];
    }
    if (tid < 8)  sb2[tid]  = bt2[ocol0 + tid];
    if (tid < 64) sMemL[tid] = 0.f;
    __syncthreads();

    // phase A: 128 outputs (8b x 16c), 4 k-groups of 128
    const int oa = tid & 127, qa = tid >> 7;
    const int ba = oa >> 4, ca = oa & 15;
    // phase B: 64 outputs (8b x 8c), 8 k-groups of 128
    const int ob = tid & 63, qb = tid >> 6;
    const int bb = ob >> 3, cb = ob & 7;

    // prefetch ytp[0]
    float ytp_reg = 0.f;
    if (tid < 128)
        ytp_reg = __ldcg(&g_ytp[(size_t)ba*(2*DD) + col0 + ca]);

    for (int t = 0; t < TT; t++) {
        // ---- phase A: h = gelu(ytp[t] + mem @ Wt1[512:]) for this CTA's 16 cols ----
        float pa = 0.f;
        if (t > 0) {
            float4* st4 = (float4*)sStage;          // mem rows: 129-float4 stride
            const float4* mem4 = (const float4*)g_mem;
            #pragma unroll
            for (int rep = 0; rep < 2; rep++) {     // 8 x 128 float4 = 16KB
                int i = tid + rep*512;
                int bi = i >> 7, k4 = i & 127;
                st4[bi*129 + k4] = __ldcg(mem4 + i);
            }
            __syncthreads();
            const float4* xs = (const float4*)sStage + ba*129 + qa*32;
            const float4* ws = (const float4*)(sW1 + ca*516) + qa*32;
            #pragma unroll
            for (int i = 0; i < 32; i++) {
                float4 xv = xs[i], wv = ws[i];
                pa += xv.x*wv.x + xv.y*wv.y + xv.z*wv.z + xv.w*wv.w;
            }
        }
        sRed[tid] = pa;
        __syncthreads();
        if (tid < 128) {
            float s = ytp_reg;
            #pragma unroll
            for (int j = 0; j < 4; j++) s += sRed[oa + j*128];
            g_hstep[ba*(2*DD) + col0 + ca] = gelu_f(s);   // bt1 already in ytp
        }
        grid_barrier(2*t + 1);

        // ---- phase B: prop = h @ Wt2 + bt2; gated mem update for 8 cols ----
        {
            float4* st4 = (float4*)sStage;          // h rows: 257-float4 stride
            const float4* h4 = (const float4*)g_hstep;
            #pragma unroll
            for (int rep = 0; rep < 4; rep++) {     // 8 x 256 float4 = 32KB
                int i = tid + rep*512;
                int bi = i >> 8, k4 = i & 255;
                st4[bi*257 + k4] = __ldcg(h4 + i);
            }
            __syncthreads();
            const float4* xs = (const float4*)sStage + bb*257 + qb*32;
            const float4* ws = (const float4*)(sW2 + cb*1028) + qb*32;
            float pb = 0.f;
            #pragma unroll
            for (int i = 0; i < 32; i++) {
                float4 xv = xs[i], wv = ws[i];
                pb += xv.x*wv.x + xv.y*wv.y + xv.z*wv.z + xv.w*wv.w;
            }
            sRed[tid] = pb;
            __syncthreads();
            if (tid < 64) {
                float s = sb2[cb];
                #pragma unroll
                for (int j = 0; j < 8; j++) s += sRed[ob + j*64];
                float gate = 1.0f / (1.0f + expf(-s));
                float mnew = sMemL[ob] * (1.0f - gate) + s * gate;
                sMemL[ob] = mnew;
                g_mem[bb*DD + ocol0 + cb] = mnew;
            }
            // prefetch ytp for next step (read-only; safe before barrier)
            if (tid < 128 && t + 1 < TT)
                ytp_reg = __ldcg(&g_ytp[(size_t)(t+1)*(BB*2*DD) + (size_t)ba*(2*DD) + col0 + ca]);
        }
        grid_barrier(2*t + 2);
    }
}

// ---------------- final: out = mem_final @ Wo + bo ----------------
__global__ void out_kernel(const float* __restrict__ Wo, const float* __restrict__ bo,
                           float* __restrict__ out) {
    __shared__ float smv[DD];
    int b = blockIdx.x, c = threadIdx.x;   // 8 blocks x 512 threads
    smv[c] = g_mem[b*DD + c];
    __syncthreads();
    float s = bo[c];
    #pragma unroll 8
    for (int k = 0; k < DD; k++) s = fmaf(smv[k], Wo[(size_t)k*DD + c], s);
    out[b*DD + c] = s;
}

// ---------------- launcher ----------------
extern "C" void kernel_launch(void* const* d_in, const int* in_sizes, int n_in,
                              void* d_out, int out_size) {
    const float* x    = (const float*)d_in[0];
    const float* Wq   = (const float*)d_in[1];
    const float* bq   = (const float*)d_in[2];
    const float* Wk   = (const float*)d_in[3];
    const float* bk   = (const float*)d_in[4];
    const float* W1   = (const float*)d_in[5];
    const float* b1   = (const float*)d_in[6];
    const float* W2   = (const float*)d_in[7];
    const float* b2   = (const float*)d_in[8];
    const float* ln_g = (const float*)d_in[9];
    const float* ln_b = (const float*)d_in[10];
    const float* Wt1  = (const float*)d_in[11];
    const float* bt1  = (const float*)d_in[12];
    const float* Wt2  = (const float*)d_in[13];
    const float* bt2  = (const float*)d_in[14];
    const float* Wo   = (const float*)d_in[15];
    const float* bo   = (const float*)d_in[16];
    float* out = (float*)d_out;

    float *p_gath, *p_h1, *p_y, *p_ytp;
    cudaGetSymbolAddress((void**)&p_gath, g_gathered);
    cudaGetSymbolAddress((void**)&p_h1,   g_h1);
    cudaGetSymbolAddress((void**)&p_y,    g_y);
    cudaGetSymbolAddress((void**)&p_ytp,  g_ytp);

    const int SMEM_S2 = (16*516 + 8*1028 + 8*1028 + 512 + 64 + 8) * (int)sizeof(float);
    cudaFuncSetAttribute(s2_kernel, cudaFuncAttributeMaxDynamicSharedMemorySize, SMEM_S2);

    // Router
    qk_kernel<<<NROWS, 128>>>(x, Wq, bq, Wk, bk);
    topk_gather<<<dim3(TT/128, BB), 128>>>(x);

    // System1: h1 = gelu(gathered@W1+b1); y = h1@W2+b2+gathered; LN(y)
    sgemm_k<0><<<dim3(8, 128), 256>>>(p_gath, W1, p_h1, b1, nullptr, NROWS, 1024, 512, 1024);
    sgemm_k<1><<<dim3(4, 128), 256>>>(p_h1, W2, p_y, b2, p_gath, NROWS, 512, 1024, 512);
    ln_kernel<<<NROWS, 256>>>(p_y, ln_g, ln_b);

    // Hoisted projection: ytp[t][b][:] = y_bt @ Wt1[:512,:] + bt1  (timestep-major)
    sgemm_k<2><<<dim3(8, 128), 256>>>(p_y, Wt1, p_ytp, bt1, nullptr, NROWS, 1024, 512, 1024);

    // System2 persistent recurrence
    s2_reset<<<1, 1>>>();
    s2_kernel<<<NCTA2, 512, SMEM_S2>>>(Wt1, Wt2, bt2);

    // Output projection
    out_kernel<<<BB, 512>>>(Wo, bo, out);
}

// round 15
// speedup vs baseline: 1.1800x; 1.1800x over previous
#include <cuda_runtime.h>
#include <cuda_bf16.h>
#include <math.h>

#define BB 8
#define TT 2048
#define DD 512
#define KQ 32
#define NROWS (BB*TT)          // 16384
#define NCTA2 128              // persistent system2 CTAs

// ---------------- device scratch (__device__ globals: allocation-free rule) ----------------
__device__ float g_q[NROWS*KQ];
__device__ float g_k[NROWS*KQ];
__device__ float g_gathered[NROWS*DD];        // 32MB
__device__ float g_h1[NROWS*2*DD];            // 64MB
__device__ float g_y[NROWS*DD];               // 32MB (pre-LN y)
__device__ float g_ytp[TT*BB*2*DD];           // 64MB, timestep-major [t][b][1024]; = LN(y)@Wt1[:512]+bt1
__device__ float g_hstep[BB*2*DD];            // per-step hidden after gelu [b][1024]
__device__ float g_mem[BB*DD];                // current memory [b][512]
__device__ float2 g_rstat[4*NROWS];           // per-row partial {sum, sumsq} from sgemm1 (4 col-blocks)
__device__ float g_u1[2*DD];                  // ln_g @ Wt1
__device__ float g_u2[2*DD];                  // ln_b @ Wt1 + bt1
// barrier state on separate 128B lines
__device__ __align__(128) unsigned g_arrive_buf[32];
__device__ __align__(128) unsigned g_gen_buf[32];
#define g_arrive (g_arrive_buf[0])
#define g_gen    (((volatile unsigned*)g_gen_buf)[0])

__device__ __forceinline__ float gelu_f(float x) {
    return 0.5f * x * (1.0f + erff(x * 0.70710678118654752f));
}

// ---------------- K1: q/k projections + u1/u2 prep (extra blocks) ----------------
__global__ void qk_kernel(const float* __restrict__ x,
                          const float* __restrict__ Wq, const float* __restrict__ bq,
                          const float* __restrict__ Wk, const float* __restrict__ bk,
                          const float* __restrict__ Wt1, const float* __restrict__ bt1,
                          const float* __restrict__ lng, const float* __restrict__ lnb) {
    int r = blockIdx.x;
    int tid = threadIdx.x;           // 128
    if (r >= NROWS) {
        // prep blocks: compute u1[c] = sum_k lng[k]*Wt1[k][c]; u2[c] = sum_k lnb[k]*Wt1[k][c] + bt1[c]
        __shared__ float sg[DD], sb[DD];
        #pragma unroll
        for (int i = 0; i < 4; i++) { sg[tid + i*128] = lng[tid + i*128]; sb[tid + i*128] = lnb[tid + i*128]; }
        __syncthreads();
        int c = (r - NROWS) * 128 + tid;   // 8 blocks x 128 = 1024
        float a = 0.f, b = 0.f;
        #pragma unroll 4
        for (int k = 0; k < DD; k++) {
            float wk = Wt1[(size_t)k*1024 + c];
            a = fmaf(sg[k], wk, a);
            b = fmaf(sb[k], wk, b);
        }
        g_u1[c] = a;
        g_u2[c] = b + bt1[c];
        return;
    }
    __shared__ float xs[DD];
    ((float4*)xs)[tid] = ((const float4*)(x + (size_t)r*DD))[tid];
    __syncthreads();
    int o = tid >> 1;                // 0..63 ; 0..31 -> q cols, 32..63 -> k cols
    int half = tid & 1;
    int j = o & 31;
    const float* W = (o < 32) ? Wq : Wk;
    float s = 0.f;
    #pragma unroll 8
    for (int d = half; d < DD; d += 2) s = fmaf(xs[d], W[d*KQ + j], s);
    s += __shfl_down_sync(0xffffffffu, s, 1);
    if (half == 0) {
        float bias = (o < 32) ? bq[j] : bk[j];
        float* out = (o < 32) ? g_q : g_k;
        out[(size_t)r*KQ + j] = s + bias;
    }
}

// ---------------- K2: per-row top-4 + gather-mean ----------------
__global__ void topk_gather(const float* __restrict__ x) {
    int b = blockIdx.y;
    int t0 = blockIdx.x * 128;
    int tid = threadIdx.x;           // 128; each owns one t-row
    __shared__ float sk[128*KQ];
    __shared__ int sidx[128][4];

    float4 q4[8];
    const float4* qr = (const float4*)(g_q + ((size_t)b*TT + t0 + tid)*KQ);
    #pragma unroll
    for (int i = 0; i < 8; i++) q4[i] = qr[i];

    float v0=-3.4e38f, v1=-3.4e38f, v2=-3.4e38f, v3=-3.4e38f;
    int i0=0, i1=0, i2=0, i3=0;

    for (int s0 = 0; s0 < TT; s0 += 128) {
        __syncthreads();
        const float4* kr = (const float4*)(g_k + ((size_t)b*TT + s0)*KQ);
        #pragma unroll
        for (int i = 0; i < 8; i++) ((float4*)sk)[tid + i*128] = kr[tid + i*128];
        __syncthreads();
        for (int ss = 0; ss < 128; ss++) {
            const float4* kk = (const float4*)(sk + ss*KQ);
            float sim = 0.f;
            #pragma unroll
            for (int i = 0; i < 8; i++) {
                float4 kv = kk[i];
                sim += q4[i].x*kv.x + q4[i].y*kv.y + q4[i].z*kv.z + q4[i].w*kv.w;
            }
            int s = s0 + ss;
            if (sim > v3) {                      // strict > : earlier index wins ties (jax top_k)
                if (sim > v1) {
                    if (sim > v0) { v3=v2;i3=i2; v2=v1;i2=i1; v1=v0;i1=i0; v0=sim;i0=s; }
                    else          { v3=v2;i3=i2; v2=v1;i2=i1; v1=sim;i1=s; }
                } else {
                    if (sim > v2) { v3=v2;i3=i2; v2=sim;i2=s; }
                    else          { v3=sim;i3=s; }
                }
            }
        }
    }
    sidx[tid][0]=i0; sidx[tid][1]=i1; sidx[tid][2]=i2; sidx[tid][3]=i3;
    __syncthreads();

    int d = tid * 4;  // cooperative gather-mean: 128 threads x 4 dims per row
    for (int tt = 0; tt < 128; tt++) {
        int j0 = sidx[tt][0], j1 = sidx[tt][1], j2 = sidx[tt][2], j3 = sidx[tt][3];
        float4 a = *(const float4*)(x + ((size_t)b*TT + j0)*DD + d);
        float4 c = *(const float4*)(x + ((size_t)b*TT + j1)*DD + d);
        float4 e = *(const float4*)(x + ((size_t)b*TT + j2)*DD + d);
        float4 f = *(const float4*)(x + ((size_t)b*TT + j3)*DD + d);
        float4 o;
        o.x = 0.25f*(a.x + c.x + e.x + f.x);
        o.y = 0.25f*(a.y + c.y + e.y + f.y);
        o.z = 0.25f*(a.z + c.z + e.z + f.z);
        o.w = 0.25f*(a.w + c.w + e.w + f.w);
        *(float4*)(g_gathered + ((size_t)b*TT + t0 + tt)*DD + d) = o;
    }
}

// ---------------- 128x128x8 fp32 SGEMM core (mode0: gelu epilogue) ----------------
__global__ void __launch_bounds__(256) sgemm0_k(
    const float* __restrict__ A, const float* __restrict__ B,
    float* __restrict__ C, const float* __restrict__ bias,
    int M, int N, int K, int ldb)
{
    __shared__ float As[8][128];
    __shared__ float Bs[8][128];
    const int tid = threadIdx.x;
    const int tx = tid & 15, ty = tid >> 4;
    const int row0 = blockIdx.y * 128, col0 = blockIdx.x * 128;
    const int arow = tid >> 1, acol = (tid & 1) << 2;
    const int brow = tid >> 5, bcol = (tid & 31) << 2;
    const float* Ap = A + (size_t)(row0 + arow) * K + acol;
    const float* Bp = B + (size_t)brow * ldb + col0 + bcol;
    float acc[8][8];
    #pragma unroll
    for (int i = 0; i < 8; i++)
        #pragma unroll
        for (int j = 0; j < 8; j++) acc[i][j] = 0.f;

    for (int k0 = 0; k0 < K; k0 += 8) {
        float4 av = *(const float4*)Ap; Ap += 8;
        float4 bv = *(const float4*)Bp; Bp += (size_t)8 * ldb;
        As[acol+0][arow] = av.x; As[acol+1][arow] = av.y;
        As[acol+2][arow] = av.z; As[acol+3][arow] = av.w;
        *(float4*)&Bs[brow][bcol] = bv;
        __syncthreads();
        #pragma unroll
        for (int kk = 0; kk < 8; kk++) {
            float a[8], bb2[8];
            *(float4*)&a[0]   = *(const float4*)&As[kk][ty*4];
            *(float4*)&a[4]   = *(const float4*)&As[kk][64 + ty*4];
            *(float4*)&bb2[0] = *(const float4*)&Bs[kk][tx*4];
            *(float4*)&bb2[4] = *(const float4*)&Bs[kk][64 + tx*4];
            #pragma unroll
            for (int i = 0; i < 8; i++)
                #pragma unroll
                for (int j = 0; j < 8; j++)
                    acc[i][j] = fmaf(a[i], bb2[j], acc[i][j]);
        }
        __syncthreads();
    }

    #pragma unroll
    for (int ih = 0; ih < 2; ih++)
    #pragma unroll
    for (int ii = 0; ii < 4; ii++) {
        int r = row0 + ih*64 + ty*4 + ii;
        #pragma unroll
        for (int jh = 0; jh < 2; jh++) {
            int c = col0 + jh*64 + tx*4;
            float4 v;
            v.x = gelu_f(acc[ih*4+ii][jh*4+0] + bias[c+0]);
            v.y = gelu_f(acc[ih*4+ii][jh*4+1] + bias[c+1]);
            v.z = gelu_f(acc[ih*4+ii][jh*4+2] + bias[c+2]);
            v.w = gelu_f(acc[ih*4+ii][jh*4+3] + bias[c+3]);
            *(float4*)(C + (size_t)r*N + c) = v;
        }
    }
}

// ---------------- SGEMM mode1 + deterministic per-row partial stats ----------------
// C = A@B + bias + res ; also writes g_rstat[blockIdx.x*NROWS + r] = {sum128, sumsq128}
__global__ void __launch_bounds__(256) sgemm1_stats_k(
    const float* __restrict__ A, const float* __restrict__ B,
    float* __restrict__ C, const float* __restrict__ bias,
    const float* __restrict__ res, int M, int N, int K, int ldb)
{
    __shared__ float As[8][128];
    __shared__ float Bs[8][128];
    const int tid = threadIdx.x;
    const int tx = tid & 15, ty = tid >> 4;
    const int row0 = blockIdx.y * 128, col0 = blockIdx.x * 128;
    const int arow = tid >> 1, acol = (tid & 1) << 2;
    const int brow = tid >> 5, bcol = (tid & 31) << 2;
    const float* Ap = A + (size_t)(row0 + arow) * K + acol;
    const float* Bp = B + (size_t)brow * ldb + col0 + bcol;
    float acc[8][8];
    #pragma unroll
    for (int i = 0; i < 8; i++)
        #pragma unroll
        for (int j = 0; j < 8; j++) acc[i][j] = 0.f;

    for (int k0 = 0; k0 < K; k0 += 8) {
        float4 av = *(const float4*)Ap; Ap += 8;
        float4 bv = *(const float4*)Bp; Bp += (size_t)8 * ldb;
        As[acol+0][arow] = av.x; As[acol+1][arow] = av.y;
        As[acol+2][arow] = av.z; As[acol+3][arow] = av.w;
        *(float4*)&Bs[brow][bcol] = bv;
        __syncthreads();
        #pragma unroll
        for (int kk = 0; kk < 8; kk++) {
            float a[8], bb2[8];
            *(float4*)&a[0]   = *(const float4*)&As[kk][ty*4];
            *(float4*)&a[4]   = *(const float4*)&As[kk][64 + ty*4];
            *(float4*)&bb2[0] = *(const float4*)&Bs[kk][tx*4];
            *(float4*)&bb2[4] = *(const float4*)&Bs[kk][64 + tx*4];
            #pragma unroll
            for (int i = 0; i < 8; i++)
                #pragma unroll
                for (int j = 0; j < 8; j++)
                    acc[i][j] = fmaf(a[i], bb2[j], acc[i][j]);
        }
        __syncthreads();
    }

    #pragma unroll
    for (int ih = 0; ih < 2; ih++)
    #pragma unroll
    for (int ii = 0; ii < 4; ii++) {
        int r = row0 + ih*64 + ty*4 + ii;
        float s = 0.f, ss = 0.f;
        #pragma unroll
        for (int jh = 0; jh < 2; jh++) {
            int c = col0 + jh*64 + tx*4;
            float4 rv = *(const float4*)(res + (size_t)r*N + c);
            float4 v;
            v.x = acc[ih*4+ii][jh*4+0] + bias[c+0] + rv.x;
            v.y = acc[ih*4+ii][jh*4+1] + bias[c+1] + rv.y;
            v.z = acc[ih*4+ii][jh*4+2] + bias[c+2] + rv.z;
            v.w = acc[ih*4+ii][jh*4+3] + bias[c+3] + rv.w;
            *(float4*)(C + (size_t)r*N + c) = v;
            s  += v.x + v.y + v.z + v.w;
            ss += v.x*v.x + v.y*v.y + v.z*v.z + v.w*v.w;
        }
        // reduce over the 16 tx lanes (half-warp groups)
        #pragma unroll
        for (int o = 8; o; o >>= 1) {
            s  += __shfl_down_sync(0xffffffffu, s,  o, 16);
            ss += __shfl_down_sync(0xffffffffu, ss, o, 16);
        }
        if (tx == 0)
            g_rstat[(size_t)blockIdx.x*NROWS + r] = make_float2(s, ss);
    }
}

// ---------------- SGEMM with fused LayerNorm: ytp = LN(y)@Wt1[:512] + bt1, timestep-major ----------------
// acc = (y .* lng) @ Wt1 ; out = inv*acc - inv*mu*u1[c] + u2[c]
__global__ void __launch_bounds__(256) sgemm_lnfold_k(
    const float* __restrict__ A, const float* __restrict__ B,
    float* __restrict__ C, const float* __restrict__ lng,
    int M, int N, int K, int ldb)
{
    __shared__ float As[8][128];
    __shared__ float Bs[8][128];
    __shared__ float smu[128], sinv[128];
    const int tid = threadIdx.x;
    const int tx = tid & 15, ty = tid >> 4;
    const int row0 = blockIdx.y * 128, col0 = blockIdx.x * 128;
    const int arow = tid >> 1, acol = (tid & 1) << 2;
    const int brow = tid >> 5, bcol = (tid & 31) << 2;
    const float* Ap = A + (size_t)(row0 + arow) * K + acol;
    const float* Bp = B + (size_t)brow * ldb + col0 + bcol;
    const float* Gp = lng + acol;

    if (tid < 128) {   // per-row LN stats from the 4 deterministic partials
        int r = row0 + tid;
        float s = 0.f, ss = 0.f;
        #pragma unroll
        for (int cb = 0; cb < 4; cb++) {
            float2 p = g_rstat[(size_t)cb*NROWS + r];
            s += p.x; ss += p.y;
        }
        float mu  = s * (1.0f/512.0f);
        float var = ss * (1.0f/512.0f) - mu*mu;
        smu[tid]  = mu;
        sinv[tid] = rsqrtf(var + 1e-5f);
    }

    float acc[8][8];
    #pragma unroll
    for (int i = 0; i < 8; i++)
        #pragma unroll
        for (int j = 0; j < 8; j++) acc[i][j] = 0.f;

    for (int k0 = 0; k0 < K; k0 += 8) {
        float4 av = *(const float4*)Ap; Ap += 8;
        float4 gv = *(const float4*)(Gp + k0);
        av.x *= gv.x; av.y *= gv.y; av.z *= gv.z; av.w *= gv.w;
        float4 bv = *(const float4*)Bp; Bp += (size_t)8 * ldb;
        As[acol+0][arow] = av.x; As[acol+1][arow] = av.y;
        As[acol+2][arow] = av.z; As[acol+3][arow] = av.w;
        *(float4*)&Bs[brow][bcol] = bv;
        __syncthreads();
        #pragma unroll
        for (int kk = 0; kk < 8; kk++) {
            float a[8], bb2[8];
            *(float4*)&a[0]   = *(const float4*)&As[kk][ty*4];
            *(float4*)&a[4]   = *(const float4*)&As[kk][64 + ty*4];
            *(float4*)&bb2[0] = *(const float4*)&Bs[kk][tx*4];
            *(float4*)&bb2[4] = *(const float4*)&Bs[kk][64 + tx*4];
            #pragma unroll
            for (int i = 0; i < 8; i++)
                #pragma unroll
                for (int j = 0; j < 8; j++)
                    acc[i][j] = fmaf(a[i], bb2[j], acc[i][j]);
        }
        __syncthreads();
    }

    #pragma unroll
    for (int ih = 0; ih < 2; ih++)
    #pragma unroll
    for (int ii = 0; ii < 4; ii++) {
        int rl = ih*64 + ty*4 + ii;
        int r = row0 + rl;
        float inv = sinv[rl];
        float nimu = -inv * smu[rl];
        int t = r & (TT-1), b = r >> 11;
        #pragma unroll
        for (int jh = 0; jh < 2; jh++) {
            int c = col0 + jh*64 + tx*4;
            float4 u1v = *(const float4*)(g_u1 + c);
            float4 u2v = *(const float4*)(g_u2 + c);
            float4 v;
            v.x = fmaf(inv, acc[ih*4+ii][jh*4+0], fmaf(nimu, u1v.x, u2v.x));
            v.y = fmaf(inv, acc[ih*4+ii][jh*4+1], fmaf(nimu, u1v.y, u2v.y));
            v.z = fmaf(inv, acc[ih*4+ii][jh*4+2], fmaf(nimu, u1v.z, u2v.z));
            v.w = fmaf(inv, acc[ih*4+ii][jh*4+3], fmaf(nimu, u1v.w, u2v.w));
            *(float4*)(C + (size_t)t*(BB*2*DD) + (size_t)b*(2*DD) + c) = v;
        }
    }
}

// ---------------- grid barrier (monotonic ticket, nanosleep poll) ----------------
__device__ __forceinline__ void grid_barrier(unsigned target) {
    __threadfence();               // release my prior global writes
    __syncthreads();
    if (threadIdx.x == 0) {
        unsigned ticket = atomicAdd(&g_arrive, 1u);
        if (ticket == target * NCTA2 - 1u) {
            g_gen = target;        // release store after strong atomic
        } else {
            while (g_gen < target) { __nanosleep(64); }
        }
        __threadfence();           // acquire
    }
    __syncthreads();
}

// ---------------- System2: persistent cooperative recurrence (128 CTAs) ----------------
// CTA ci owns h-cols [8ci,8ci+8) and prop/mem-cols [4ci,4ci+4); weights stationary in SMEM.
__global__ void __launch_bounds__(512, 1) s2_kernel(
    const float* __restrict__ Wt1, const float* __restrict__ Wt2,
    const float* __restrict__ bt2)
{
    extern __shared__ float sm[];
    float* sW1    = sm;                 // 8 x 516
    float* sW2    = sW1 + 8*516;        // 4 x 1028
    float* sStage = sW2 + 4*1028;       // 8 rows x 1028 floats (257 float4 stride)
    float* sRed   = sStage + 8*1028;    // 512
    float* sMemL  = sRed + 512;         // 32 : this CTA's mem slice [b][c]
    float* sb2    = sMemL + 32;         // 4

    const int tid = threadIdx.x;
    const int ci = blockIdx.x;
    const int col0 = ci * 8;
    const int ocol0 = ci * 4;

    #pragma unroll
    for (int rep = 0; rep < 8; rep++) {
        int i = tid + rep*512;
        int c = i >> 9, k = i & 511;
        sW1[c*516 + k] = Wt1[(size_t)(512 + k)*1024 + col0 + c];
    }
    #pragma unroll
    for (int rep = 0; rep < 8; rep++) {
        int i = tid + rep*512;
        int c = i >> 10, k = i & 1023;
        sW2[c*1028 + k] = Wt2[(size_t)k*512 + ocol0 + c];
    }
    if (tid < 4)  sb2[tid]  = bt2[ocol0 + tid];
    if (tid < 32) sMemL[tid] = 0.f;
    __syncthreads();

    const int oa = tid & 63, qa = tid >> 6;   // A: 64 outputs x 8 k-groups(64)
    const int ba = oa >> 3, ca = oa & 7;
    const int ob = tid & 31, qb = tid >> 5;   // B: 32 outputs x 16 k-groups(64)
    const int bb = ob >> 2, cb = ob & 3;

    // prefetch ytp[0]
    float ytp_reg = 0.f;
    if (tid < 64)
        ytp_reg = __ldcg(&g_ytp[(size_t)ba*(2*DD) + col0 + ca]);

    for (int t = 0; t < TT; t++) {
        // ---- phase A: h = gelu(ytp[t] + mem @ Wt1[512:]) for this CTA's 8 cols ----
        float pa = 0.f;
        if (t > 0) {
            float4* st4 = (float4*)sStage;
            const float4* mem4 = (const float4*)g_mem;
            #pragma unroll
            for (int rep = 0; rep < 2; rep++) {                // 8 x 128 float4
                int i = tid + rep*512;
                int bi = i >> 7, k4 = i & 127;
                st4[bi*257 + k4] = __ldcg(mem4 + i);
            }
            __syncthreads();
            const float4* xs = (const float4*)sStage + ba*257 + qa*16;
            const float4* ws = (const float4*)(sW1 + ca*516 + qa*64);
            #pragma unroll
            for (int i = 0; i < 16; i++) {
                float4 xv = xs[i], wv = ws[i];
                pa += xv.x*wv.x + xv.y*wv.y + xv.z*wv.z + xv.w*wv.w;
            }
        }
        sRed[tid] = pa;
        __syncthreads();
        if (tid < 64) {
            float s = ytp_reg;
            #pragma unroll
            for (int j = 0; j < 8; j++) s += sRed[oa + j*64];
            g_hstep[ba*(2*DD) + col0 + ca] = gelu_f(s);   // bt1 already in ytp
        }
        grid_barrier(2*t + 1);

        // ---- phase B: prop = h @ Wt2 + bt2; gated mem update for 4 cols ----
        {
            float4* st4 = (float4*)sStage;
            const float4* h4 = (const float4*)g_hstep;
            #pragma unroll
            for (int rep = 0; rep < 4; rep++) {                // 8 x 256 float4
                int i = tid + rep*512;
                int bi = i >> 8, k4 = i & 255;
                st4[bi*257 + k4] = __ldcg(h4 + i);
            }
            __syncthreads();
            const float4* xs = (const float4*)sStage + bb*257 + qb*16;
            const float4* ws = (const float4*)(sW2 + cb*1028 + qb*64);
            float pb = 0.f;
            #pragma unroll
            for (int i = 0; i < 16; i++) {
                float4 xv = xs[i], wv = ws[i];
                pb += xv.x*wv.x + xv.y*wv.y + xv.z*wv.z + xv.w*wv.w;
            }
            sRed[tid] = pb;
            __syncthreads();
            if (tid < 32) {
                float s = sb2[cb];
                #pragma unroll
                for (int j = 0; j < 16; j++) s += sRed[ob + j*32];
                float gate = 1.0f / (1.0f + expf(-s));
                float mnew = sMemL[ob] * (1.0f - gate) + s * gate;
                sMemL[ob] = mnew;
                g_mem[bb*DD + ocol0 + cb] = mnew;
            }
            // prefetch ytp for next step (read-only; safe before barrier)
            if (tid < 64 && t + 1 < TT)
                ytp_reg = __ldcg(&g_ytp[(size_t)(t+1)*(BB*2*DD) + (size_t)ba*(2*DD) + col0 + ca]);
        }
        grid_barrier(2*t + 2);
    }
}

// ---------------- final: out = mem_final @ Wo + bo ; also reset barrier state ----------------
__global__ void out_kernel(const float* __restrict__ Wo, const float* __restrict__ bo,
                           float* __restrict__ out) {
    __shared__ float smv[DD];
    int b = blockIdx.x, c = threadIdx.x;   // 8 blocks x 512 threads
    if (b == 0 && c == 0) { g_arrive = 0u; g_gen = 0u; }   // s2 finished (stream order); safe
    smv[c] = g_mem[b*DD + c];
    __syncthreads();
    float s = bo[c];
    #pragma unroll 8
    for (int k = 0; k < DD; k++) s = fmaf(smv[k], Wo[(size_t)k*DD + c], s);
    out[b*DD + c] = s;
}

// ---------------- launcher ----------------
extern "C" void kernel_launch(void* const* d_in, const int* in_sizes, int n_in,
                              void* d_out, int out_size) {
    const float* x    = (const float*)d_in[0];
    const float* Wq   = (const float*)d_in[1];
    const float* bq   = (const float*)d_in[2];
    const float* Wk   = (const float*)d_in[3];
    const float* bk   = (const float*)d_in[4];
    const float* W1   = (const float*)d_in[5];
    const float* b1   = (const float*)d_in[6];
    const float* W2   = (const float*)d_in[7];
    const float* b2   = (const float*)d_in[8];
    const float* ln_g = (const float*)d_in[9];
    const float* ln_b = (const float*)d_in[10];
    const float* Wt1  = (const float*)d_in[11];
    const float* bt1  = (const float*)d_in[12];
    const float* Wt2  = (const float*)d_in[13];
    const float* bt2  = (const float*)d_in[14];
    const float* Wo   = (const float*)d_in[15];
    const float* bo   = (const float*)d_in[16];
    float* out = (float*)d_out;

    float *p_gath, *p_h1, *p_y, *p_ytp;
    cudaGetSymbolAddress((void**)&p_gath, g_gathered);
    cudaGetSymbolAddress((void**)&p_h1,   g_h1);
    cudaGetSymbolAddress((void**)&p_y,    g_y);
    cudaGetSymbolAddress((void**)&p_ytp,  g_ytp);

    const int SMEM_S2 = (8*516 + 4*1028 + 8*1028 + 512 + 32 + 4) * (int)sizeof(float);
    cudaFuncSetAttribute(s2_kernel, cudaFuncAttributeMaxDynamicSharedMemorySize, SMEM_S2);

    // (1) Router projections + u1/u2 prep in 8 extra blocks
    qk_kernel<<<NROWS + 8, 128>>>(x, Wq, bq, Wk, bk, Wt1, bt1, ln_g, ln_b);
    // (2) top-4 + gather-mean
    topk_gather<<<dim3(TT/128, BB), 128>>>(x);
    // (3) h1 = gelu(gathered@W1+b1)
    sgemm0_k<<<dim3(8, 128), 256>>>(p_gath, W1, p_h1, b1, NROWS, 1024, 512, 1024);
    // (4) y = h1@W2+b2+gathered, with deterministic per-row LN partials
    sgemm1_stats_k<<<dim3(4, 128), 256>>>(p_h1, W2, p_y, b2, p_gath, NROWS, 512, 1024, 512);
    // (5) ytp = LN(y)@Wt1[:512]+bt1, timestep-major (LN fused)
    sgemm_lnfold_k<<<dim3(8, 128), 256>>>(p_y, Wt1, p_ytp, ln_g, NROWS, 1024, 512, 1024);
    // (6) System2 persistent recurrence (barrier state zeroed statically / by previous out_kernel)
    s2_kernel<<<NCTA2, 512, SMEM_S2>>>(Wt1, Wt2, bt2);
    // (7) output projection + barrier-state reset for next replay
    out_kernel<<<BB, 512>>>(Wo, bo, out);
}

// round 17
// speedup vs baseline: 1.2484x; 1.0580x over previous
#include <cuda_runtime.h>
#include <cuda_bf16.h>
#include <math.h>

#define BB 8
#define TT 2048
#define DD 512
#define KQ 32
#define NROWS (BB*TT)          // 16384
#define NCTA2 128              // persistent system2 CTAs: 4 groups x 32
#define GSIZE 32               // CTAs per group

// ---------------- device scratch (__device__ globals: allocation-free rule) ----------------
__device__ float g_q[NROWS*KQ];
__device__ float g_k[NROWS*KQ];
__device__ float g_gathered[NROWS*DD];        // 32MB
__device__ float g_h1[NROWS*2*DD];            // 64MB
__device__ float g_y[NROWS*DD];               // 32MB (pre-LN y)
__device__ float g_ytp[TT*BB*2*DD];           // 64MB, timestep-major [t][b][1024]; = LN(y)@Wt1[:512]+bt1
__device__ float g_hstep[BB*2*DD];            // per-step hidden after gelu [b][1024]
__device__ float g_mem[BB*DD];                // current memory [b][512]
__device__ float2 g_rstat[4*NROWS];           // per-row partial {sum, sumsq} from sgemm1 (4 col-blocks)
__device__ float g_u1[2*DD];                  // ln_g @ Wt1
__device__ float g_u2[2*DD];                  // ln_b @ Wt1 + bt1
// per-group barrier state, one 128B line per group per array
__device__ __align__(128) unsigned g_garr[4][32];
__device__ __align__(128) unsigned g_ggen[4][32];

__device__ __forceinline__ float gelu_f(float x) {
    return 0.5f * x * (1.0f + erff(x * 0.70710678118654752f));
}

// ---------------- K1: q/k projections + u1/u2 prep (extra blocks) ----------------
__global__ void qk_kernel(const float* __restrict__ x,
                          const float* __restrict__ Wq, const float* __restrict__ bq,
                          const float* __restrict__ Wk, const float* __restrict__ bk,
                          const float* __restrict__ Wt1, const float* __restrict__ bt1,
                          const float* __restrict__ lng, const float* __restrict__ lnb) {
    int r = blockIdx.x;
    int tid = threadIdx.x;           // 128
    if (r >= NROWS) {
        __shared__ float sg[DD], sb[DD];
        #pragma unroll
        for (int i = 0; i < 4; i++) { sg[tid + i*128] = lng[tid + i*128]; sb[tid + i*128] = lnb[tid + i*128]; }
        __syncthreads();
        int c = (r - NROWS) * 128 + tid;   // 8 blocks x 128 = 1024
        float a = 0.f, b = 0.f;
        #pragma unroll 4
        for (int k = 0; k < DD; k++) {
            float wk = Wt1[(size_t)k*1024 + c];
            a = fmaf(sg[k], wk, a);
            b = fmaf(sb[k], wk, b);
        }
        g_u1[c] = a;
        g_u2[c] = b + bt1[c];
        return;
    }
    __shared__ float xs[DD];
    ((float4*)xs)[tid] = ((const float4*)(x + (size_t)r*DD))[tid];
    __syncthreads();
    int o = tid >> 1;                // 0..63 ; 0..31 -> q cols, 32..63 -> k cols
    int half = tid & 1;
    int j = o & 31;
    const float* W = (o < 32) ? Wq : Wk;
    float s = 0.f;
    #pragma unroll 8
    for (int d = half; d < DD; d += 2) s = fmaf(xs[d], W[d*KQ + j], s);
    s += __shfl_down_sync(0xffffffffu, s, 1);
    if (half == 0) {
        float bias = (o < 32) ? bq[j] : bk[j];
        float* out = (o < 32) ? g_q : g_k;
        out[(size_t)r*KQ + j] = s + bias;
    }
}

// ---------------- K2: per-row top-4 + gather-mean ----------------
__global__ void topk_gather(const float* __restrict__ x) {
    int b = blockIdx.y;
    int t0 = blockIdx.x * 128;
    int tid = threadIdx.x;           // 128; each owns one t-row
    __shared__ float sk[128*KQ];
    __shared__ int sidx[128][4];

    float4 q4[8];
    const float4* qr = (const float4*)(g_q + ((size_t)b*TT + t0 + tid)*KQ);
    #pragma unroll
    for (int i = 0; i < 8; i++) q4[i] = qr[i];

    float v0=-3.4e38f, v1=-3.4e38f, v2=-3.4e38f, v3=-3.4e38f;
    int i0=0, i1=0, i2=0, i3=0;

    for (int s0 = 0; s0 < TT; s0 += 128) {
        __syncthreads();
        const float4* kr = (const float4*)(g_k + ((size_t)b*TT + s0)*KQ);
        #pragma unroll
        for (int i = 0; i < 8; i++) ((float4*)sk)[tid + i*128] = kr[tid + i*128];
        __syncthreads();
        for (int ss = 0; ss < 128; ss++) {
            const float4* kk = (const float4*)(sk + ss*KQ);
            float sim = 0.f;
            #pragma unroll
            for (int i = 0; i < 8; i++) {
                float4 kv = kk[i];
                sim += q4[i].x*kv.x + q4[i].y*kv.y + q4[i].z*kv.z + q4[i].w*kv.w;
            }
            int s = s0 + ss;
            if (sim > v3) {                      // strict > : earlier index wins ties (jax top_k)
                if (sim > v1) {
                    if (sim > v0) { v3=v2;i3=i2; v2=v1;i2=i1; v1=v0;i1=i0; v0=sim;i0=s; }
                    else          { v3=v2;i3=i2; v2=v1;i2=i1; v1=sim;i1=s; }
                } else {
                    if (sim > v2) { v3=v2;i3=i2; v2=sim;i2=s; }
                    else          { v3=sim;i3=s; }
                }
            }
        }
    }
    sidx[tid][0]=i0; sidx[tid][1]=i1; sidx[tid][2]=i2; sidx[tid][3]=i3;
    __syncthreads();

    int d = tid * 4;  // cooperative gather-mean: 128 threads x 4 dims per row
    for (int tt = 0; tt < 128; tt++) {
        int j0 = sidx[tt][0], j1 = sidx[tt][1], j2 = sidx[tt][2], j3 = sidx[tt][3];
        float4 a = *(const float4*)(x + ((size_t)b*TT + j0)*DD + d);
        float4 c = *(const float4*)(x + ((size_t)b*TT + j1)*DD + d);
        float4 e = *(const float4*)(x + ((size_t)b*TT + j2)*DD + d);
        float4 f = *(const float4*)(x + ((size_t)b*TT + j3)*DD + d);
        float4 o;
        o.x = 0.25f*(a.x + c.x + e.x + f.x);
        o.y = 0.25f*(a.y + c.y + e.y + f.y);
        o.z = 0.25f*(a.z + c.z + e.z + f.z);
        o.w = 0.25f*(a.w + c.w + e.w + f.w);
        *(float4*)(g_gathered + ((size_t)b*TT + t0 + tt)*DD + d) = o;
    }
}

// ---------------- 128x128x8 fp32 SGEMM core (mode0: gelu epilogue) ----------------
__global__ void __launch_bounds__(256) sgemm0_k(
    const float* __restrict__ A, const float* __restrict__ B,
    float* __restrict__ C, const float* __restrict__ bias,
    int M, int N, int K, int ldb)
{
    __shared__ float As[8][128];
    __shared__ float Bs[8][128];
    const int tid = threadIdx.x;
    const int tx = tid & 15, ty = tid >> 4;
    const int row0 = blockIdx.y * 128, col0 = blockIdx.x * 128;
    const int arow = tid >> 1, acol = (tid & 1) << 2;
    const int brow = tid >> 5, bcol = (tid & 31) << 2;
    const float* Ap = A + (size_t)(row0 + arow) * K + acol;
    const float* Bp = B + (size_t)brow * ldb + col0 + bcol;
    float acc[8][8];
    #pragma unroll
    for (int i = 0; i < 8; i++)
        #pragma unroll
        for (int j = 0; j < 8; j++) acc[i][j] = 0.f;

    for (int k0 = 0; k0 < K; k0 += 8) {
        float4 av = *(const float4*)Ap; Ap += 8;
        float4 bv = *(const float4*)Bp; Bp += (size_t)8 * ldb;
        As[acol+0][arow] = av.x; As[acol+1][arow] = av.y;
        As[acol+2][arow] = av.z; As[acol+3][arow] = av.w;
        *(float4*)&Bs[brow][bcol] = bv;
        __syncthreads();
        #pragma unroll
        for (int kk = 0; kk < 8; kk++) {
            float a[8], bb2[8];
            *(float4*)&a[0]   = *(const float4*)&As[kk][ty*4];
            *(float4*)&a[4]   = *(const float4*)&As[kk][64 + ty*4];
            *(float4*)&bb2[0] = *(const float4*)&Bs[kk][tx*4];
            *(float4*)&bb2[4] = *(const float4*)&Bs[kk][64 + tx*4];
            #pragma unroll
            for (int i = 0; i < 8; i++)
                #pragma unroll
                for (int j = 0; j < 8; j++)
                    acc[i][j] = fmaf(a[i], bb2[j], acc[i][j]);
        }
        __syncthreads();
    }

    #pragma unroll
    for (int ih = 0; ih < 2; ih++)
    #pragma unroll
    for (int ii = 0; ii < 4; ii++) {
        int r = row0 + ih*64 + ty*4 + ii;
        #pragma unroll
        for (int jh = 0; jh < 2; jh++) {
            int c = col0 + jh*64 + tx*4;
            float4 v;
            v.x = gelu_f(acc[ih*4+ii][jh*4+0] + bias[c+0]);
            v.y = gelu_f(acc[ih*4+ii][jh*4+1] + bias[c+1]);
            v.z = gelu_f(acc[ih*4+ii][jh*4+2] + bias[c+2]);
            v.w = gelu_f(acc[ih*4+ii][jh*4+3] + bias[c+3]);
            *(float4*)(C + (size_t)r*N + c) = v;
        }
    }
}

// ---------------- SGEMM mode1 + deterministic per-row partial stats ----------------
__global__ void __launch_bounds__(256) sgemm1_stats_k(
    const float* __restrict__ A, const float* __restrict__ B,
    float* __restrict__ C, const float* __restrict__ bias,
    const float* __restrict__ res, int M, int N, int K, int ldb)
{
    __shared__ float As[8][128];
    __shared__ float Bs[8][128];
    const int tid = threadIdx.x;
    const int tx = tid & 15, ty = tid >> 4;
    const int row0 = blockIdx.y * 128, col0 = blockIdx.x * 128;
    const int arow = tid >> 1, acol = (tid & 1) << 2;
    const int brow = tid >> 5, bcol = (tid & 31) << 2;
    const float* Ap = A + (size_t)(row0 + arow) * K + acol;
    const float* Bp = B + (size_t)brow * ldb + col0 + bcol;
    float acc[8][8];
    #pragma unroll
    for (int i = 0; i < 8; i++)
        #pragma unroll
        for (int j = 0; j < 8; j++) acc[i][j] = 0.f;

    for (int k0 = 0; k0 < K; k0 += 8) {
        float4 av = *(const float4*)Ap; Ap += 8;
        float4 bv = *(const float4*)Bp; Bp += (size_t)8 * ldb;
        As[acol+0][arow] = av.x; As[acol+1][arow] = av.y;
        As[acol+2][arow] = av.z; As[acol+3][arow] = av.w;
        *(float4*)&Bs[brow][bcol] = bv;
        __syncthreads();
        #pragma unroll
        for (int kk = 0; kk < 8; kk++) {
            float a[8], bb2[8];
            *(float4*)&a[0]   = *(const float4*)&As[kk][ty*4];
            *(float4*)&a[4]   = *(const float4*)&As[kk][64 + ty*4];
            *(float4*)&bb2[0] = *(const float4*)&Bs[kk][tx*4];
            *(float4*)&bb2[4] = *(const float4*)&Bs[kk][64 + tx*4];
            #pragma unroll
            for (int i = 0; i < 8; i++)
                #pragma unroll
                for (int j = 0; j < 8; j++)
                    acc[i][j] = fmaf(a[i], bb2[j], acc[i][j]);
        }
        __syncthreads();
    }

    #pragma unroll
    for (int ih = 0; ih < 2; ih++)
    #pragma unroll
    for (int ii = 0; ii < 4; ii++) {
        int r = row0 + ih*64 + ty*4 + ii;
        float s = 0.f, ss = 0.f;
        #pragma unroll
        for (int jh = 0; jh < 2; jh++) {
            int c = col0 + jh*64 + tx*4;
            float4 rv = *(const float4*)(res + (size_t)r*N + c);
            float4 v;
            v.x = acc[ih*4+ii][jh*4+0] + bias[c+0] + rv.x;
            v.y = acc[ih*4+ii][jh*4+1] + bias[c+1] + rv.y;
            v.z = acc[ih*4+ii][jh*4+2] + bias[c+2] + rv.z;
            v.w = acc[ih*4+ii][jh*4+3] + bias[c+3] + rv.w;
            *(float4*)(C + (size_t)r*N + c) = v;
            s  += v.x + v.y + v.z + v.w;
            ss += v.x*v.x + v.y*v.y + v.z*v.z + v.w*v.w;
        }
        #pragma unroll
        for (int o = 8; o; o >>= 1) {
            s  += __shfl_down_sync(0xffffffffu, s,  o, 16);
            ss += __shfl_down_sync(0xffffffffu, ss, o, 16);
        }
        if (tx == 0)
            g_rstat[(size_t)blockIdx.x*NROWS + r] = make_float2(s, ss);
    }
}

// ---------------- SGEMM with fused LayerNorm: ytp = LN(y)@Wt1[:512] + bt1, timestep-major ----------------
__global__ void __launch_bounds__(256) sgemm_lnfold_k(
    const float* __restrict__ A, const float* __restrict__ B,
    float* __restrict__ C, const float* __restrict__ lng,
    int M, int N, int K, int ldb)
{
    __shared__ float As[8][128];
    __shared__ float Bs[8][128];
    __shared__ float smu[128], sinv[128];
    const int tid = threadIdx.x;
    const int tx = tid & 15, ty = tid >> 4;
    const int row0 = blockIdx.y * 128, col0 = blockIdx.x * 128;
    const int arow = tid >> 1, acol = (tid & 1) << 2;
    const int brow = tid >> 5, bcol = (tid & 31) << 2;
    const float* Ap = A + (size_t)(row0 + arow) * K + acol;
    const float* Bp = B + (size_t)brow * ldb + col0 + bcol;
    const float* Gp = lng + acol;

    if (tid < 128) {   // per-row LN stats from the 4 deterministic partials
        int r = row0 + tid;
        float s = 0.f, ss = 0.f;
        #pragma unroll
        for (int cb = 0; cb < 4; cb++) {
            float2 p = g_rstat[(size_t)cb*NROWS + r];
            s += p.x; ss += p.y;
        }
        float mu  = s * (1.0f/512.0f);
        float var = ss * (1.0f/512.0f) - mu*mu;
        smu[tid]  = mu;
        sinv[tid] = rsqrtf(var + 1e-5f);
    }

    float acc[8][8];
    #pragma unroll
    for (int i = 0; i < 8; i++)
        #pragma unroll
        for (int j = 0; j < 8; j++) acc[i][j] = 0.f;

    for (int k0 = 0; k0 < K; k0 += 8) {
        float4 av = *(const float4*)Ap; Ap += 8;
        float4 gv = *(const float4*)(Gp + k0);
        av.x *= gv.x; av.y *= gv.y; av.z *= gv.z; av.w *= gv.w;
        float4 bv = *(const float4*)Bp; Bp += (size_t)8 * ldb;
        As[acol+0][arow] = av.x; As[acol+1][arow] = av.y;
        As[acol+2][arow] = av.z; As[acol+3][arow] = av.w;
        *(float4*)&Bs[brow][bcol] = bv;
        __syncthreads();
        #pragma unroll
        for (int kk = 0; kk < 8; kk++) {
            float a[8], bb2[8];
            *(float4*)&a[0]   = *(const float4*)&As[kk][ty*4];
            *(float4*)&a[4]   = *(const float4*)&As[kk][64 + ty*4];
            *(float4*)&bb2[0] = *(const float4*)&Bs[kk][tx*4];
            *(float4*)&bb2[4] = *(const float4*)&Bs[kk][64 + tx*4];
            #pragma unroll
            for (int i = 0; i < 8; i++)
                #pragma unroll
                for (int j = 0; j < 8; j++)
                    acc[i][j] = fmaf(a[i], bb2[j], acc[i][j]);
        }
        __syncthreads();
    }

    #pragma unroll
    for (int ih = 0; ih < 2; ih++)
    #pragma unroll
    for (int ii = 0; ii < 4; ii++) {
        int rl = ih*64 + ty*4 + ii;
        int r = row0 + rl;
        float inv = sinv[rl];
        float nimu = -inv * smu[rl];
        int t = r & (TT-1), b = r >> 11;
        #pragma unroll
        for (int jh = 0; jh < 2; jh++) {
            int c = col0 + jh*64 + tx*4;
            float4 u1v = *(const float4*)(g_u1 + c);
            float4 u2v = *(const float4*)(g_u2 + c);
            float4 v;
            v.x = fmaf(inv, acc[ih*4+ii][jh*4+0], fmaf(nimu, u1v.x, u2v.x));
            v.y = fmaf(inv, acc[ih*4+ii][jh*4+1], fmaf(nimu, u1v.y, u2v.y));
            v.z = fmaf(inv, acc[ih*4+ii][jh*4+2], fmaf(nimu, u1v.z, u2v.z));
            v.w = fmaf(inv, acc[ih*4+ii][jh*4+3], fmaf(nimu, u1v.w, u2v.w));
            *(float4*)(C + (size_t)t*(BB*2*DD) + (size_t)b*(2*DD) + c) = v;
        }
    }
}

// ---------------- per-group barrier (32 arrivals, monotonic ticket, nanosleep poll) ----------------
__device__ __forceinline__ void group_barrier(int g, unsigned target) {
    __threadfence();               // release my prior global writes
    __syncthreads();
    if (threadIdx.x == 0) {
        unsigned ticket = atomicAdd(&g_garr[g][0], 1u);
        if (ticket == target * GSIZE - 1u) {
            *(volatile unsigned*)&g_ggen[g][0] = target;
        } else {
            while (*(volatile unsigned*)&g_ggen[g][0] < target) { __nanosleep(64); }
        }
        __threadfence();           // acquire
    }
    __syncthreads();
}

// ---------------- System2: 4 independent groups of 32 CTAs (one batch-pair each) ----------------
// Group g handles batches {2g, 2g+1}. CTA j in group owns h-cols [32j,32j+32) and
// mem-cols [16j,16j+16) for both batches; weights stationary in SMEM (128 KB).
__global__ void __launch_bounds__(512, 1) s2_kernel(
    const float* __restrict__ Wt1, const float* __restrict__ Wt2,
    const float* __restrict__ bt2)
{
    extern __shared__ float sm[];
    float* sW1    = sm;                 // 32 x 516
    float* sW2    = sW1 + 32*516;       // 16 x 1028
    float* sStage = sW2 + 16*1028;      // up to 514 float4 (= 2056 floats)
    float* sRed   = sStage + 2056;      // 512
    float* sMemL  = sRed + 512;         // 32 : [beta][16] local mem slice
    float* sb2    = sMemL + 32;         // 16

    const int tid = threadIdx.x;
    const int g  = blockIdx.x >> 5;     // group 0..3
    const int j  = blockIdx.x & 31;     // CTA within group
    const int b0 = 2*g;                 // first batch of pair
    const int col0  = j * 32;           // h-col base
    const int ocol0 = j * 16;           // mem-col base

    #pragma unroll
    for (int rep = 0; rep < 32; rep++) {            // 32 cols x 512 k
        int i = tid + rep*512;
        int c = i >> 9, k = i & 511;
        sW1[c*516 + k] = Wt1[(size_t)(512 + k)*1024 + col0 + c];
    }
    #pragma unroll
    for (int rep = 0; rep < 32; rep++) {            // 16 cols x 1024 k
        int i = tid + rep*512;
        int c = i >> 10, k = i & 1023;
        sW2[c*1028 + k] = Wt2[(size_t)k*512 + ocol0 + c];
    }
    if (tid < 16) sb2[tid]  = bt2[ocol0 + tid];
    if (tid < 32) sMemL[tid] = 0.f;
    __syncthreads();

    // phase A: 64 outputs (2 beta x 32 cols), 8 k-groups of 64 (dot len 512)
    const int oa = tid & 63, qa = tid >> 6;
    const int bA = oa >> 5, cA = oa & 31;
    // phase B: 32 outputs (2 beta x 16 cols), 16 k-groups of 64 (dot len 1024)
    const int ob = tid & 31, qb = tid >> 5;
    const int bB = ob >> 4, cB = ob & 15;

    // prefetch ytp[0]
    float ytp_reg = 0.f;
    if (tid < 64)
        ytp_reg = __ldcg(&g_ytp[(size_t)(b0 + bA)*(2*DD) + col0 + cA]);

    for (int t = 0; t < TT; t++) {
        // ---- phase A: h = gelu(ytp[t] + mem @ Wt1[512:]) for this CTA's 2x32 cols ----
        float pa = 0.f;
        if (t > 0) {
            float4* st4 = (float4*)sStage;                 // mem rows: 129-float4 stride
            const float4* mem4 = (const float4*)g_mem;
            if (tid < 256) {                               // 2 x 128 float4
                int bi = tid >> 7, k4 = tid & 127;
                st4[bi*129 + k4] = __ldcg(mem4 + (b0 + bi)*128 + k4);
            }
            __syncthreads();
            const float4* xs = (const float4*)sStage + bA*129 + qa*16;
            const float4* ws = (const float4*)(sW1 + cA*516 + qa*64);
            #pragma unroll
            for (int i = 0; i < 16; i++) {
                float4 xv = xs[i], wv = ws[i];
                pa += xv.x*wv.x + xv.y*wv.y + xv.z*wv.z + xv.w*wv.w;
            }
        }
        sRed[tid] = pa;
        __syncthreads();
        if (tid < 64) {
            float s = ytp_reg;
            #pragma unroll
            for (int r8 = 0; r8 < 8; r8++) s += sRed[oa + r8*64];
            g_hstep[(size_t)(b0 + bA)*(2*DD) + col0 + cA] = gelu_f(s);  // bt1 already in ytp
        }
        group_barrier(g, 2*t + 1);

        // ---- phase B: prop = h @ Wt2 + bt2; gated mem update for this CTA's 2x16 cols ----
        {
            float4* st4 = (float4*)sStage;                 // h rows: 257-float4 stride
            const float4* h4 = (const float4*)g_hstep;
            {                                              // 2 x 256 float4
                int bi = tid >> 8, k4 = tid & 255;
                st4[bi*257 + k4] = __ldcg(h4 + (b0 + bi)*256 + k4);
            }
            __syncthreads();
            const float4* xs = (const float4*)sStage + bB*257 + qb*16;
            const float4* ws = (const float4*)(sW2 + cB*1028 + qb*64);
            float pb = 0.f;
            #pragma unroll
            for (int i = 0; i < 16; i++) {
                float4 xv = xs[i], wv = ws[i];
                pb += xv.x*wv.x + xv.y*wv.y + xv.z*wv.z + xv.w*wv.w;
            }
            sRed[tid] = pb;
            __syncthreads();
            if (tid < 32) {
                float s = sb2[cB];
                #pragma unroll
                for (int r16 = 0; r16 < 16; r16++) s += sRed[ob + r16*32];
                float gate = 1.0f / (1.0f + expf(-s));
                float mnew = sMemL[ob] * (1.0f - gate) + s * gate;
                sMemL[ob] = mnew;
                g_mem[(size_t)(b0 + bB)*DD + ocol0 + cB] = mnew;
            }
            // prefetch ytp for next step (read-only; safe before barrier)
            if (tid < 64 && t + 1 < TT)
                ytp_reg = __ldcg(&g_ytp[(size_t)(t+1)*(BB*2*DD) + (size_t)(b0 + bA)*(2*DD) + col0 + cA]);
        }
        group_barrier(g, 2*t + 2);
    }
}

// ---------------- final: out = mem_final @ Wo + bo ; also reset barrier state ----------------
__global__ void out_kernel(const float* __restrict__ Wo, const float* __restrict__ bo,
                           float* __restrict__ out) {
    __shared__ float smv[DD];
    int b = blockIdx.x, c = threadIdx.x;   // 8 blocks x 512 threads
    if (b == 0 && c < 4) { g_garr[c][0] = 0u; g_ggen[c][0] = 0u; }  // s2 done (stream order)
    smv[c] = g_mem[b*DD + c];
    __syncthreads();
    float s = bo[c];
    #pragma unroll 8
    for (int k = 0; k < DD; k++) s = fmaf(smv[k], Wo[(size_t)k*DD + c], s);
    out[b*DD + c] = s;
}

// ---------------- launcher ----------------
extern "C" void kernel_launch(void* const* d_in, const int* in_sizes, int n_in,
                              void* d_out, int out_size) {
    const float* x    = (const float*)d_in[0];
    const float* Wq   = (const float*)d_in[1];
    const float* bq   = (const float*)d_in[2];
    const float* Wk   = (const float*)d_in[3];
    const float* bk   = (const float*)d_in[4];
    const float* W1   = (const float*)d_in[5];
    const float* b1   = (const float*)d_in[6];
    const float* W2   = (const float*)d_in[7];
    const float* b2   = (const float*)d_in[8];
    const float* ln_g = (const float*)d_in[9];
    const float* ln_b = (const float*)d_in[10];
    const float* Wt1  = (const float*)d_in[11];
    const float* bt1  = (const float*)d_in[12];
    const float* Wt2  = (const float*)d_in[13];
    const float* bt2  = (const float*)d_in[14];
    const float* Wo   = (const float*)d_in[15];
    const float* bo   = (const float*)d_in[16];
    float* out = (float*)d_out;

    float *p_gath, *p_h1, *p_y, *p_ytp;
    cudaGetSymbolAddress((void**)&p_gath, g_gathered);
    cudaGetSymbolAddress((void**)&p_h1,   g_h1);
    cudaGetSymbolAddress((void**)&p_y,    g_y);
    cudaGetSymbolAddress((void**)&p_ytp,  g_ytp);

    const int SMEM_S2 = (32*516 + 16*1028 + 2056 + 512 + 32 + 16) * (int)sizeof(float);
    cudaFuncSetAttribute(s2_kernel, cudaFuncAttributeMaxDynamicSharedMemorySize, SMEM_S2);

    // (1) Router projections + u1/u2 prep in 8 extra blocks
    qk_kernel<<<NROWS + 8, 128>>>(x, Wq, bq, Wk, bk, Wt1, bt1, ln_g, ln_b);
    // (2) top-4 + gather-mean
    topk_gather<<<dim3(TT/128, BB), 128>>>(x);
    // (3) h1 = gelu(gathered@W1+b1)
    sgemm0_k<<<dim3(8, 128), 256>>>(p_gath, W1, p_h1, b1, NROWS, 1024, 512, 1024);
    // (4) y = h1@W2+b2+gathered, with deterministic per-row LN partials
    sgemm1_stats_k<<<dim3(4, 128), 256>>>(p_h1, W2, p_y, b2, p_gath, NROWS, 512, 1024, 512);
    // (5) ytp = LN(y)@Wt1[:512]+bt1, timestep-major (LN fused)
    sgemm_lnfold_k<<<dim3(8, 128), 256>>>(p_y, Wt1, p_ytp, ln_g, NROWS, 1024, 512, 1024);
    // (6) System2: 4 independent batch-pair groups of 32 CTAs
    s2_kernel<<<NCTA2, 512, SMEM_S2>>>(Wt1, Wt2, bt2);
    // (7) output projection + barrier-state reset for next replay
    out_kernel<<<BB, 512>>>(Wo, bo, out);
}